// round 1
// baseline (speedup 1.0000x reference)
#include <cuda_runtime.h>

#define B_  16
#define C_  256
#define H_  64
#define W_  64
#define K_  31
#define PAD_ 15
#define HW_ 4096
#define TILE_W 94   // 64 + 30 halo
#define TILE_S 95   // padded row stride (odd -> conflict-free across rows)

// Scratch (allocation-free rule: __device__ globals)
__device__ float g_y[(size_t)B_ * C_ * HW_];     // dwconv output, 256 MB
__device__ float g_psum[C_ * B_];
__device__ float g_psumsq[C_ * B_];
__device__ float g_scale[C_];
__device__ float g_bias[C_];

// ---------------------------------------------------------------------------
// Kernel 1: depthwise 31x31 conv, one (b,c) 64x64 image per block,
// fused per-block sum / sumsq partials.
// ---------------------------------------------------------------------------
__global__ __launch_bounds__(256) void dwconv_kernel(const float* __restrict__ x,
                                                     const float* __restrict__ dw) {
    __shared__ float tile[TILE_W * TILE_S];
    __shared__ float wsm[K_ * K_];
    __shared__ float red[2][8];

    const int bx  = blockIdx.x;
    const int c   = bx & (C_ - 1);
    const int b   = bx >> 8;
    const int tid = threadIdx.x;

    // weights for this channel
    const float* wp = dw + c * (K_ * K_);
    for (int i = tid; i < K_ * K_; i += 256) wsm[i] = wp[i];

    // input tile with zero-padded halo
    const float* xp = x + (size_t)(b * C_ + c) * HW_;
    for (int i = tid; i < TILE_W * TILE_W; i += 256) {
        int tr = i / TILE_W;
        int tc = i - tr * TILE_W;
        int gh = tr - PAD_;
        int gw = tc - PAD_;
        float v = 0.0f;
        if ((unsigned)gh < (unsigned)H_ && (unsigned)gw < (unsigned)W_)
            v = xp[gh * W_ + gw];
        tile[tr * TILE_S + tc] = v;
    }
    __syncthreads();

    // thread -> (row h, col block w0): warp spans 32 consecutive rows, same w0
    const int h  = tid & 63;
    const int w0 = (tid >> 6) << 4;   // 0,16,32,48

    float acc[16];
    #pragma unroll
    for (int j = 0; j < 16; ++j) acc[j] = 0.0f;

    #pragma unroll 1
    for (int kh = 0; kh < K_; ++kh) {
        const float* xr = &tile[(h + kh) * TILE_S + w0];
        const float* wr = &wsm[kh * K_];
        float win[46];
        #pragma unroll
        for (int t = 0; t < 46; ++t) win[t] = xr[t];
        #pragma unroll
        for (int kw = 0; kw < K_; ++kw) {
            const float wt = wr[kw];
            #pragma unroll
            for (int j = 0; j < 16; ++j)
                acc[j] = fmaf(win[kw + j], wt, acc[j]);
        }
    }

    // store y and accumulate statistics
    float* yp = g_y + (size_t)(b * C_ + c) * HW_ + h * W_ + w0;
    float s = 0.0f, s2 = 0.0f;
    #pragma unroll
    for (int j = 0; j < 16; ++j) {
        yp[j] = acc[j];
        s  += acc[j];
        s2  = fmaf(acc[j], acc[j], s2);
    }
    #pragma unroll
    for (int off = 16; off > 0; off >>= 1) {
        s  += __shfl_down_sync(0xffffffffu, s,  off);
        s2 += __shfl_down_sync(0xffffffffu, s2, off);
    }
    const int warp = tid >> 5;
    const int lane = tid & 31;
    if (lane == 0) { red[0][warp] = s; red[1][warp] = s2; }
    __syncthreads();
    if (tid == 0) {
        float ts = 0.0f, t2 = 0.0f;
        #pragma unroll
        for (int w = 0; w < 8; ++w) { ts += red[0][w]; t2 += red[1][w]; }
        g_psum[c * B_ + b]   = ts;
        g_psumsq[c * B_ + b] = t2;
    }
}

// ---------------------------------------------------------------------------
// Kernel 2: fold B partials per channel -> scale/bias  (deterministic)
// ---------------------------------------------------------------------------
__global__ void stats_kernel(const float* __restrict__ gamma,
                             const float* __restrict__ beta) {
    const int c = threadIdx.x;
    float s = 0.0f, s2 = 0.0f;
    #pragma unroll
    for (int b = 0; b < B_; ++b) {
        s  += g_psum[c * B_ + b];
        s2 += g_psumsq[c * B_ + b];
    }
    const float inv  = 1.0f / (float)(B_ * HW_);
    const float mean = s * inv;
    const float var  = s2 * inv - mean * mean;
    const float rstd = rsqrtf(var + 1e-5f);
    const float sc   = rstd * gamma[c];
    g_scale[c] = sc;
    g_bias[c]  = beta[c] - mean * sc;
}

// ---------------------------------------------------------------------------
// Kernel 3: fused normalize+ReLU+pointwise GEMM
// out[b,o,hw] = sum_c pw[o,c] * relu(y[b,c,hw]*scale[c] + bias[c])
// Tile: 64 (o) x 64 (pixels), K-step 16, 4x4 micro-tile per thread.
// ---------------------------------------------------------------------------
__global__ __launch_bounds__(256) void pw_kernel(const float* __restrict__ pw,
                                                 float* __restrict__ out) {
    __shared__ float As[16][64];   // As[k][m] = pw[m0+m, c0+k]
    __shared__ float Bs[16][64];   // Bs[k][n] = relu(y*scale+bias)

    const int b   = blockIdx.z;
    const int m0  = blockIdx.y * 64;
    const int hw0 = blockIdx.x * 64;
    const int tid = threadIdx.x;
    const int tm  = tid >> 4;      // 0..15
    const int tn  = tid & 15;      // 0..15

    // loader indices
    const int la_m  = tid >> 2;        // 0..63
    const int la_k4 = (tid & 3) * 4;   // 0,4,8,12
    const int lb_k  = tid >> 4;        // 0..15
    const int lb_n  = (tid & 15) * 4;  // 0..60

    const float* yb = g_y + (size_t)b * C_ * HW_ + hw0;

    float acc[4][4];
    #pragma unroll
    for (int i = 0; i < 4; ++i)
        #pragma unroll
        for (int j = 0; j < 4; ++j) acc[i][j] = 0.0f;

    for (int c0 = 0; c0 < C_; c0 += 16) {
        // A tile
        float4 a4 = *(const float4*)&pw[(m0 + la_m) * C_ + c0 + la_k4];
        As[la_k4 + 0][la_m] = a4.x;
        As[la_k4 + 1][la_m] = a4.y;
        As[la_k4 + 2][la_m] = a4.z;
        As[la_k4 + 3][la_m] = a4.w;
        // B tile with fused normalize + relu
        {
            const int cc = c0 + lb_k;
            float4 b4 = *(const float4*)&yb[(size_t)cc * HW_ + lb_n];
            const float sc = g_scale[cc];
            const float bi = g_bias[cc];
            b4.x = fmaxf(fmaf(b4.x, sc, bi), 0.0f);
            b4.y = fmaxf(fmaf(b4.y, sc, bi), 0.0f);
            b4.z = fmaxf(fmaf(b4.z, sc, bi), 0.0f);
            b4.w = fmaxf(fmaf(b4.w, sc, bi), 0.0f);
            *(float4*)&Bs[lb_k][lb_n] = b4;
        }
        __syncthreads();

        #pragma unroll
        for (int kk = 0; kk < 16; ++kk) {
            const float4 av = *(const float4*)&As[kk][tm * 4];
            const float4 bv = *(const float4*)&Bs[kk][tn * 4];
            const float a_[4] = {av.x, av.y, av.z, av.w};
            const float b_[4] = {bv.x, bv.y, bv.z, bv.w};
            #pragma unroll
            for (int i = 0; i < 4; ++i)
                #pragma unroll
                for (int j = 0; j < 4; ++j)
                    acc[i][j] = fmaf(a_[i], b_[j], acc[i][j]);
        }
        __syncthreads();
    }

    // write 4x4 micro-tile
    #pragma unroll
    for (int i = 0; i < 4; ++i) {
        const int o = m0 + tm * 4 + i;
        float4 ov;
        ov.x = acc[i][0]; ov.y = acc[i][1]; ov.z = acc[i][2]; ov.w = acc[i][3];
        *(float4*)&out[(size_t)(b * C_ + o) * HW_ + hw0 + tn * 4] = ov;
    }
}

// ---------------------------------------------------------------------------
extern "C" void kernel_launch(void* const* d_in, const int* in_sizes, int n_in,
                              void* d_out, int out_size) {
    const float* x     = (const float*)d_in[0];  // (16,256,64,64)
    const float* dw    = (const float*)d_in[1];  // (256,1,31,31)
    const float* gamma = (const float*)d_in[2];  // (256,)
    const float* beta  = (const float*)d_in[3];  // (256,)
    const float* pw    = (const float*)d_in[4];  // (256,256)
    float* out = (float*)d_out;                  // (16,256,64,64)

    dwconv_kernel<<<B_ * C_, 256>>>(x, dw);
    stats_kernel<<<1, C_>>>(gamma, beta);
    pw_kernel<<<dim3(HW_ / 64, C_ / 64, B_), 256>>>(pw, out);
}